// round 17
// baseline (speedup 1.0000x reference)
#include <cuda_runtime.h>
#include <cuda_bf16.h>
#include <cuda_fp16.h>
#include <cstdint>

#define P_ 16
#define B_ 4
#define C_ 256
#define N_ 256
#define PB_ 64

typedef __nv_bfloat16 bf16;

// ---------------- gmem scratch ----------------
__device__ __align__(16) bf16  g_corr_h[(size_t)PB_ * N_ * C_];  // corr split [pb][j][d]
__device__ __align__(16) bf16  g_corr_l[(size_t)PB_ * N_ * C_];
__device__ __align__(16) unsigned short g_tf_f16[(size_t)PB_ * C_ * N_];  // temp fp16 [pb][c][i]
__device__ __align__(16) bf16  g_tfT_h[(size_t)PB_ * N_ * C_];   // temp^T split [pb][i][c]
__device__ __align__(16) bf16  g_tfT_l[(size_t)PB_ * N_ * C_];
__device__ __align__(16) bf16  g_We_h[(size_t)C_ * C_];          // We split [d][c]
__device__ __align__(16) bf16  g_We_l[(size_t)C_ * C_];
__device__ __align__(16) float g_wtf[(size_t)PB_ * N_];

// ---------------- helpers ----------------
__device__ __forceinline__ uint32_t smem_u32(const void* p) {
    uint32_t a;
    asm("{ .reg .u64 t; cvta.to.shared.u64 t, %1; cvt.u32.u64 %0, t; }" : "=r"(a) : "l"(p));
    return a;
}
__device__ __forceinline__ void ldm_x4(uint32_t& r0, uint32_t& r1, uint32_t& r2,
                                       uint32_t& r3, uint32_t a) {
    asm volatile("ldmatrix.sync.aligned.m8n8.x4.shared.b16 {%0,%1,%2,%3}, [%4];"
                 : "=r"(r0), "=r"(r1), "=r"(r2), "=r"(r3) : "r"(a));
}
__device__ __forceinline__ void mma16816(float* c, const uint32_t* a,
                                         uint32_t b0, uint32_t b1) {
    asm volatile("mma.sync.aligned.m16n8k16.row.col.f32.bf16.bf16.f32 "
                 "{%0,%1,%2,%3}, {%4,%5,%6,%7}, {%8,%9}, {%0,%1,%2,%3};"
                 : "+f"(c[0]), "+f"(c[1]), "+f"(c[2]), "+f"(c[3])
                 : "r"(a[0]), "r"(a[1]), "r"(a[2]), "r"(a[3]), "r"(b0), "r"(b1));
}
__device__ __forceinline__ void mma16816h(float* c, const uint32_t* a,
                                          uint32_t b0, uint32_t b1) {
    asm volatile("mma.sync.aligned.m16n8k16.row.col.f32.f16.f16.f32 "
                 "{%0,%1,%2,%3}, {%4,%5,%6,%7}, {%8,%9}, {%0,%1,%2,%3};"
                 : "+f"(c[0]), "+f"(c[1]), "+f"(c[2]), "+f"(c[3])
                 : "r"(a[0]), "r"(a[1]), "r"(a[2]), "r"(a[3]), "r"(b0), "r"(b1));
}
__device__ __forceinline__ uint32_t pack_f16(float lo, float hi) {
    uint32_t r;
    asm("cvt.rn.f16x2.f32 %0, %1, %2;" : "=r"(r) : "f"(hi), "f"(lo));
    return r;
}
__device__ __forceinline__ uint32_t pack2_bf16(bf16 lo, bf16 hi) {
    return ((uint32_t)__bfloat16_as_ushort(hi) << 16) | (uint32_t)__bfloat16_as_ushort(lo);
}
__device__ __forceinline__ void cpa16(uint32_t d, const void* s) {
    asm volatile("cp.async.cg.shared.global [%0], [%1], 16;" :: "r"(d), "l"(s));
}
__device__ __forceinline__ void cp_commit() {
    asm volatile("cp.async.commit_group;" ::: "memory");
}
__device__ __forceinline__ void cp_wait1() {
    asm volatile("cp.async.wait_group 1;" ::: "memory");
}
__device__ __forceinline__ void cp_wait0() {
    asm volatile("cp.async.wait_group 0;" ::: "memory");
}
__device__ __forceinline__ float inv_patch(const void* p) {
    if (p == nullptr) return 1.f / 16.f;
    int iv = *(const int*)p;
    if (iv >= 1 && iv <= 65536) return 1.f / (float)iv;
    float fv = __int_as_float(iv);
    if (fv >= 0.5f && fv <= 65536.f) return 1.f / fv;
    return 1.f / 16.f;
}

// ---------------------------------------------------------------------------
// Prep kernels (verified R15/16)
// ---------------------------------------------------------------------------
__device__ __forceinline__ void split4(const float4 x, uint2& uh, uint2& ul) {
    bf16 h0 = __float2bfloat16(x.x), h1 = __float2bfloat16(x.y);
    bf16 h2 = __float2bfloat16(x.z), h3 = __float2bfloat16(x.w);
    bf16 l0 = __float2bfloat16(x.x - __bfloat162float(h0));
    bf16 l1 = __float2bfloat16(x.y - __bfloat162float(h1));
    bf16 l2 = __float2bfloat16(x.z - __bfloat162float(h2));
    bf16 l3 = __float2bfloat16(x.w - __bfloat162float(h3));
    uh = make_uint2(pack2_bf16(h0, h1), pack2_bf16(h2, h3));
    ul = make_uint2(pack2_bf16(l0, l1), pack2_bf16(l2, l3));
}
__global__ void __launch_bounds__(256) split_We(const float* __restrict__ We) {
    size_t i = (size_t)blockIdx.x * 256 + threadIdx.x;
    float4 x = ((const float4*)We)[i];
    uint2 uh, ul;
    split4(x, uh, ul);
    ((uint2*)g_We_h)[i] = uh;
    ((uint2*)g_We_l)[i] = ul;
}
__global__ void __launch_bounds__(256) transpose_split(const float* __restrict__ temp) {
    __shared__ float tile[32][33];
    const int pb = blockIdx.z;
    const int i0 = blockIdx.x * 32, c0 = blockIdx.y * 32;
    const int tx = threadIdx.x & 31, ty = threadIdx.x >> 5;
    const float* src = temp + (size_t)pb * C_ * N_;
#pragma unroll
    for (int k = 0; k < 4; k++) {
        int c = c0 + ty + k * 8;
        float x = src[(size_t)c * N_ + i0 + tx];
        tile[ty + k * 8][tx] = x;
        g_tf_f16[(size_t)pb * 65536 + (size_t)c * N_ + i0 + tx] =
            __half_as_ushort(__float2half(x));
    }
    __syncthreads();
#pragma unroll
    for (int k = 0; k < 4; k++) {
        int i = i0 + ty + k * 8;
        float x = tile[tx][ty + k * 8];
        size_t o = (size_t)pb * N_ * C_ + (size_t)i * C_ + c0 + tx;
        bf16 hh = __float2bfloat16(x);
        g_tfT_h[o] = hh;
        g_tfT_l[o] = __float2bfloat16(x - __bfloat162float(hh));
    }
}
__global__ void __launch_bounds__(1024) zero_wtf() {
    g_wtf[blockIdx.x * 1024 + threadIdx.x] = 0.f;
}
__global__ void __launch_bounds__(256) wtf_part(const float* __restrict__ temp,
                                                const float* __restrict__ Wg) {
    __shared__ float sWg[32];
    const int pb = blockIdx.x, cc = blockIdx.y;
    const int i = threadIdx.x;
    if (i < 32) sWg[i] = Wg[cc * 32 + i];
    __syncthreads();
    const float* src = temp + (size_t)pb * C_ * N_ + (size_t)cc * 32 * N_;
    float s = 0.f;
#pragma unroll 8
    for (int c = 0; c < 32; c++) s += src[(size_t)c * N_ + i] * sWg[c];
    atomicAdd(&g_wtf[(size_t)pb * N_ + i], s);
}

// ---------------------------------------------------------------------------
// corr via mma (verified R14-16)
// ---------------------------------------------------------------------------
#define STGC 49152

__device__ __forceinline__ void issue_cm(uint32_t sb, int buf, int t,
                                         int pb, int ih, int kc) {
    {
        const int row = t >> 1, half = t & 1;
        const bf16* src = (half ? g_We_l : g_We_h) + (size_t)row * 256 + (size_t)kc * 32;
        const uint32_t dst = sb + buf * STGC + row * 128;
        const uint32_t sw = (uint32_t)((row & 7) << 4);
#pragma unroll
        for (int v = 0; v < 4; v++)
            cpa16(dst + (((uint32_t)(half * 64 + v * 16)) ^ sw), src + v * 8);
    }
    {
#pragma unroll
        for (int u = 0; u < 2; u++) {
            const int idx = t * 2 + u;
            const int row = idx >> 3, v = idx & 7;
            const bf16* srcp = (v < 4 ? g_tfT_h : g_tfT_l) +
                               ((size_t)pb * 65536 + (size_t)(ih * 128 + row) * 256 +
                                (size_t)kc * 32 + (size_t)(v & 3) * 8);
            const uint32_t d = sb + buf * STGC + 32768 + row * 128 +
                               (((uint32_t)(v * 16)) ^ ((uint32_t)((row & 7) << 4)));
            cpa16(d, srcp);
        }
    }
}

__global__ void __launch_bounds__(512, 1)
corr_mma() {
    extern __shared__ char smd[];
    const uint32_t sb = smem_u32(smd);
    const int t = threadIdx.x;
    const int w = t >> 5, lane = t & 31;
    const int ih = blockIdx.x;
    const int pb = blockIdx.y;

    const int wj = w >> 1, wi = w & 1;
    const int a_row_off = ((lane >> 3) & 1) * 8 + (lane & 7);
    const int a_col_off = ((lane >> 4) & 1) * 16;
    const int b_row_off = ((lane >> 4) & 1) * 8 + (lane & 7);
    const int b_col_off = ((lane >> 3) & 1) * 16;

    float acc[16][4];
#pragma unroll
    for (int n = 0; n < 16; n++)
#pragma unroll
        for (int x = 0; x < 4; x++) acc[n][x] = 0.f;

    issue_cm(sb, 0, t, pb, ih, 0);
    cp_commit();

#pragma unroll 1
    for (int kc = 0; kc < 8; kc++) {
        if (kc < 7) { issue_cm(sb, (kc + 1) & 1, t, pb, ih, kc + 1); cp_commit(); }
        if (kc < 7) cp_wait1(); else cp_wait0();
        __syncthreads();
        const uint32_t bB = sb + (kc & 1) * STGC;
        const uint32_t bA = bB + 32768;
#pragma unroll
        for (int s = 0; s < 2; s++) {
            uint32_t ah[4], al[4];
            {
                const int ar = 16 * wj + a_row_off;
                const uint32_t sw = (uint32_t)((ar & 7) << 4);
                const uint32_t ad = bA + ar * 128;
                ldm_x4(ah[0], ah[1], ah[2], ah[3],
                       ad + (((uint32_t)(s * 32 + a_col_off)) ^ sw));
                ldm_x4(al[0], al[1], al[2], al[3],
                       ad + (((uint32_t)(64 + s * 32 + a_col_off)) ^ sw));
            }
#pragma unroll
            for (int np = 0; np < 8; np++) {
                const int br = 128 * wi + np * 16 + b_row_off;
                const uint32_t sw = (uint32_t)((br & 7) << 4);
                const uint32_t bd = bB + br * 128;
                uint32_t bh[4], bl[4];
                ldm_x4(bh[0], bh[1], bh[2], bh[3],
                       bd + (((uint32_t)(s * 32 + b_col_off)) ^ sw));
                ldm_x4(bl[0], bl[1], bl[2], bl[3],
                       bd + (((uint32_t)(64 + s * 32 + b_col_off)) ^ sw));
                float* e = acc[2 * np];
                float* o = acc[2 * np + 1];
                mma16816(e, ah, bh[0], bh[1]);
                mma16816(o, ah, bh[2], bh[3]);
                mma16816(e, ah, bl[0], bl[1]);
                mma16816(o, ah, bl[2], bl[3]);
                mma16816(e, al, bh[0], bh[1]);
                mma16816(o, al, bh[2], bh[3]);
            }
        }
        __syncthreads();
    }

    const int r1 = 16 * wj + (lane >> 2);
    const int r2 = r1 + 8;
#pragma unroll
    for (int nt = 0; nt < 16; nt++) {
        const int d = 128 * wi + nt * 8 + (lane & 3) * 2;
#pragma unroll
        for (int rr = 0; rr < 2; rr++) {
            const int i = ih * 128 + (rr ? r2 : r1);
            float x0 = acc[nt][rr * 2 + 0], x1 = acc[nt][rr * 2 + 1];
            bf16 h0 = __float2bfloat16(x0), h1 = __float2bfloat16(x1);
            bf16 l0 = __float2bfloat16(x0 - __bfloat162float(h0));
            bf16 l1 = __float2bfloat16(x1 - __bfloat162float(h1));
            const size_t o = (size_t)pb * 65536 + (size_t)i * 256 + d;
            *(uint32_t*)(g_corr_h + o) = pack2_bf16(h0, h1);
            *(uint32_t*)(g_corr_l + o) = pack2_bf16(l0, l1);
        }
    }
}

// ---------------------------------------------------------------------------
// Fused kernel. 128 CTAs, 512 threads. k=64 GEMM1 chunks, i=128 GEMM2 chunks.
// SMEM: [0,128K)  two 64K stage bufs.
//         G1 buf: Bh 16K | Bl 16K | Ah 16K | Al 16K  (128 rows x 128B each)
//         G2 buf: tf plane0 32K | plane1 32K          (256 rows x 128B each)
//       [128K,192K) P fp16: 4 chunks x 16K (128 rows x 128B)
//       [192K+] sWtf 1K | sSum 1K | sG 1K | sM0 1K
// Pass-0 exp stored fp16 with per-warp-row max shift m0w (no overflow);
// in-place rescale folds e^(m0w-40)*sc. 11 syncs/q.
// ---------------------------------------------------------------------------
#define STG   65536
#define PF    131072
#define SWTF  196608
#define SSUM  197632
#define SGG   198656
#define SM0V  199680
#define SMEM_TOTAL 200704
#define NT 512

__device__ __forceinline__ void issue_g1(uint32_t sb, int buf, int t,
                                         int qb, int pb, int j0, int pass, int kc) {
    const int plane = t >> 7;       // 0 Bh, 1 Bl, 2 Ah, 3 Al
    const int row = t & 127;
    const uint32_t sw = (uint32_t)((row & 7) << 4);
    const bf16* src;
    if (plane == 0)
        src = g_tfT_h + ((size_t)qb * 65536 + (size_t)(pass * 128 + row) * 256 + kc * 64);
    else if (plane == 1)
        src = g_tfT_l + ((size_t)qb * 65536 + (size_t)(pass * 128 + row) * 256 + kc * 64);
    else if (plane == 2)
        src = g_corr_h + ((size_t)pb * 65536 + (size_t)(j0 + row) * 256 + kc * 64);
    else
        src = g_corr_l + ((size_t)pb * 65536 + (size_t)(j0 + row) * 256 + kc * 64);
    const uint32_t dst = sb + buf * STG + plane * 16384 + row * 128;
#pragma unroll
    for (int v = 0; v < 8; v++)
        cpa16(dst + (((uint32_t)(v * 16)) ^ sw), src + v * 8);
}

__device__ __forceinline__ void issue_g2(uint32_t sb, int buf, int t, int qb, int kc) {
    const int plane = t >> 8, row = t & 255;
    const uint32_t sw = (uint32_t)((row & 7) << 4);
    const unsigned short* src = g_tf_f16 + (size_t)qb * 65536 + (size_t)row * 256 +
                                kc * 128 + plane * 64;
    const uint32_t dst = sb + buf * STG + plane * 32768 + row * 128;
#pragma unroll
    for (int v = 0; v < 8; v++)
        cpa16(dst + (((uint32_t)(v * 16)) ^ sw), src + v * 8);
}

__global__ void __launch_bounds__(NT, 1)
fused_mma(const void* __restrict__ pnp, float* __restrict__ out) {
    extern __shared__ char smd[];
    const uint32_t sb = smem_u32(smd);
    float* sWtf = (float*)(smd + SWTF);
    float* sSum = (float*)(smd + SSUM);   // [2][128]
    float* sG   = (float*)(smd + SGG);    // [2][128]
    float* sM0  = (float*)(smd + SM0V);   // [2][128] pass-0 per-warp row max

    const int t = threadIdx.x;
    const int w = t >> 5, lane = t & 31;
    const int jt = blockIdx.x & 1;
    const int pb = blockIdx.x >> 1;
    const int b = pb & 3;
    const int j0 = jt * 128;

    const int wj = w >> 1, wi = w & 1;      // GEMM1: 8 j-warps(16j) x 2 i-warps(64i/pass)
    const int wc = w >> 1, wj2 = w & 1;     // GEMM2: 8 c-warps(32c) x 2 j-warps(64j)
    const float invp = inv_patch(pnp);

    const int a_row_off = ((lane >> 3) & 1) * 8 + (lane & 7);
    const int a_col_off = ((lane >> 4) & 1) * 16;
    const int b_row_off = ((lane >> 4) & 1) * 8 + (lane & 7);
    const int b_col_off = ((lane >> 3) & 1) * 16;
    const int r1 = 16 * wj + (lane >> 2);
    const int r2 = r1 + 8;

    float acc2[2][8][4];
#pragma unroll
    for (int m = 0; m < 2; m++)
#pragma unroll
        for (int n = 0; n < 8; n++)
#pragma unroll
            for (int x = 0; x < 4; x++) acc2[m][n][x] = 0.f;

    issue_g1(sb, 0, t, 0 * B_ + b, pb, j0, 0, 0);
    cp_commit();

#pragma unroll 1
    for (int q = 0; q < P_; q++) {
        const int qb = q * B_ + b;
        if (t < 256) sWtf[t] = g_wtf[(size_t)qb * N_ + t];

        float srun1 = 0.f, grun1 = 0.f, srun2 = 0.f, grun2 = 0.f;
        float acc1[8][4];

        // ===== GEMM1: two i-passes, 4 k64-chunks each, bf16 3-term ===========
#pragma unroll 1
        for (int pass = 0; pass < 2; pass++) {
#pragma unroll
            for (int n = 0; n < 8; n++)
#pragma unroll
                for (int x = 0; x < 4; x++) acc1[n][x] = 0.f;

#pragma unroll 1
            for (int kc = 0; kc < 4; kc++) {
                const int step = pass * 4 + kc;   // 0..7
                cp_wait0();
                __syncthreads();
                if (step < 7) {
                    issue_g1(sb, (step + 1) & 1, t, qb, pb, j0,
                             (step + 1) >> 2, (step + 1) & 3);
                } else {
                    issue_g2(sb, 0, t, qb, 0);    // step 8 -> parity 0
                }
                cp_commit();
                const uint32_t bufb = sb + (step & 1) * STG;
#pragma unroll
                for (int s = 0; s < 4; s++) {
                    uint32_t ah[4], al[4];
                    {
                        const int ar = 16 * wj + a_row_off;
                        const uint32_t sw = (uint32_t)((ar & 7) << 4);
                        const uint32_t off = (uint32_t)(s * 32 + a_col_off);
                        ldm_x4(ah[0], ah[1], ah[2], ah[3],
                               bufb + 32768 + ar * 128 + (off ^ sw));
                        ldm_x4(al[0], al[1], al[2], al[3],
                               bufb + 49152 + ar * 128 + (off ^ sw));
                    }
#pragma unroll
                    for (int np = 0; np < 4; np++) {
                        const int br = 64 * wi + np * 16 + b_row_off;
                        const uint32_t sw = (uint32_t)((br & 7) << 4);
                        const uint32_t off = (uint32_t)(s * 32 + b_col_off);
                        uint32_t bh[4], bl[4];
                        ldm_x4(bh[0], bh[1], bh[2], bh[3],
                               bufb + br * 128 + (off ^ sw));
                        ldm_x4(bl[0], bl[1], bl[2], bl[3],
                               bufb + 16384 + br * 128 + (off ^ sw));
                        float* e = acc1[2 * np];
                        float* o = acc1[2 * np + 1];
                        mma16816(e, ah, bh[0], bh[1]);
                        mma16816(o, ah, bh[2], bh[3]);
                        mma16816(e, ah, bl[0], bl[1]);
                        mma16816(o, ah, bl[2], bl[3]);
                        mma16816(e, al, bh[0], bh[1]);
                        mma16816(o, al, bh[2], bh[3]);
                    }
                }
            }

            if (pass == 0) {
                // per-warp row max (over this warp's 64 i)
                float m1 = acc1[0][0], m2 = acc1[0][2];
#pragma unroll
                for (int nt = 0; nt < 8; nt++) {
                    m1 = fmaxf(m1, fmaxf(acc1[nt][0], acc1[nt][1]));
                    m2 = fmaxf(m2, fmaxf(acc1[nt][2], acc1[nt][3]));
                }
#pragma unroll
                for (int o = 1; o <= 2; o <<= 1) {
                    m1 = fmaxf(m1, __shfl_xor_sync(0xffffffffu, m1, o));
                    m2 = fmaxf(m2, __shfl_xor_sync(0xffffffffu, m2, o));
                }
                const float f1 = __expf(m1 - 40.f);
                const float f2 = __expf(m2 - 40.f);
                float sl1 = 0.f, gl1 = 0.f, sl2 = 0.f, gl2 = 0.f;
                char* base = smd + PF + wi * 16384;   // chunk = wi
                const uint32_t sw1 = (uint32_t)((r1 & 7) << 4);
                const uint32_t sw2 = (uint32_t)((r2 & 7) << 4);
#pragma unroll
                for (int nt = 0; nt < 8; nt++) {
                    const int col = 64 * wi + nt * 8 + (lane & 3) * 2;
                    float2 wv = *(float2*)&sWtf[col];
                    float e0 = __expf(acc1[nt][0] - m1);
                    float e1 = __expf(acc1[nt][1] - m1);
                    float e2 = __expf(acc1[nt][2] - m2);
                    float e3 = __expf(acc1[nt][3] - m2);
                    sl1 += e0 + e1; gl1 += e0 * wv.x + e1 * wv.y;
                    sl2 += e2 + e3; gl2 += e2 * wv.x + e3 * wv.y;
                    const uint32_t off = (uint32_t)(nt * 16 + (lane & 3) * 4);
                    *(uint32_t*)(base + r1 * 128 + (off ^ sw1)) = pack_f16(e0, e1);
                    *(uint32_t*)(base + r2 * 128 + (off ^ sw2)) = pack_f16(e2, e3);
                }
                srun1 += sl1 * f1; grun1 += gl1 * f1;
                srun2 += sl2 * f2; grun2 += gl2 * f2;
                if ((lane & 3) == 0) {
                    sM0[wi * 128 + r1] = m1;
                    sM0[wi * 128 + r2] = m2;
                }
            } else {
#pragma unroll
                for (int nt = 0; nt < 8; nt++) {
                    const int col = 128 + 64 * wi + nt * 8 + (lane & 3) * 2;
                    float2 wv = *(float2*)&sWtf[col];
                    float e0 = __expf(acc1[nt][0] - 40.f);
                    float e1 = __expf(acc1[nt][1] - 40.f);
                    float e2 = __expf(acc1[nt][2] - 40.f);
                    float e3 = __expf(acc1[nt][3] - 40.f);
                    acc1[nt][0] = e0; acc1[nt][1] = e1;
                    acc1[nt][2] = e2; acc1[nt][3] = e3;
                    srun1 += e0 + e1; grun1 += e0 * wv.x + e1 * wv.y;
                    srun2 += e2 + e3; grun2 += e2 * wv.x + e3 * wv.y;
                }
            }
        }

        // ===== softmax finalize =============================================
        {
#pragma unroll
            for (int o = 1; o <= 2; o <<= 1) {
                srun1 += __shfl_xor_sync(0xffffffffu, srun1, o);
                grun1 += __shfl_xor_sync(0xffffffffu, grun1, o);
                srun2 += __shfl_xor_sync(0xffffffffu, srun2, o);
                grun2 += __shfl_xor_sync(0xffffffffu, grun2, o);
            }
            if ((lane & 3) == 0) {
                sSum[wi * 128 + r1] = srun1;  sG[wi * 128 + r1] = grun1;
                sSum[wi * 128 + r2] = srun2;  sG[wi * 128 + r2] = grun2;
            }
            __syncthreads();    // [S1] sums + m0 + pass-0 P published

            // pass-1 exp -> scaled fp16, chunk 2+wi
            float sc[2];
#pragma unroll
            for (int h = 0; h < 2; h++) {
                const int r = r1 + 8 * h;
                const float tot = sSum[r] + sSum[128 + r];
                const float gt  = sG[r] + sG[128 + r];
                sc[h] = (1.f / (1.f + __expf(-gt / tot))) / tot;
            }
            {
                char* base = smd + PF + (2 + wi) * 16384;
                const uint32_t sw1 = (uint32_t)((r1 & 7) << 4);
                const uint32_t sw2 = (uint32_t)((r2 & 7) << 4);
#pragma unroll
                for (int nt = 0; nt < 8; nt++) {
                    const uint32_t off = (uint32_t)(nt * 16 + (lane & 3) * 4);
                    *(uint32_t*)(base + r1 * 128 + (off ^ sw1)) =
                        pack_f16(acc1[nt][0] * sc[0], acc1[nt][1] * sc[0]);
                    *(uint32_t*)(base + r2 * 128 + (off ^ sw2)) =
                        pack_f16(acc1[nt][2] * sc[1], acc1[nt][3] * sc[1]);
                }
            }
            // in-place rescale of pass-0 chunks (0,1): x *= sc_row * e^(m0-40)
            {
                const int ch = t >> 8;            // chunk 0 or 1
                const int rr = (t & 255) >> 1;    // row 0..127
                const int hf = t & 1;
                const float tot = sSum[rr] + sSum[128 + rr];
                const float gt  = sG[rr] + sG[128 + rr];
                const float scv = (1.f / (1.f + __expf(-gt / tot))) / tot *
                                  __expf(sM0[ch * 128 + rr] - 40.f);
                const uint32_t sw = (uint32_t)((rr & 7) << 4);
                char* row = smd + PF + ch * 16384 + rr * 128;
#pragma unroll
                for (int v = 0; v < 16; v++) {
                    uint32_t* p = (uint32_t*)(row + (((uint32_t)(hf * 64 + v * 4)) ^ sw));
                    __half2 hv = *(__half2*)p;
                    float2 fv = __half22float2(hv);
                    *p = pack_f16(fv.x * scv, fv.y * scv);
                }
            }
        }

        // ===== GEMM2: acc2 += tf_f16 . P'^T, 2 chunks of i=128 ===============
#pragma unroll 1
        for (int kc = 0; kc < 2; kc++) {
            cp_wait0();
            __syncthreads();    // tf chunk ready + P rescale/writes published
            if (kc == 0) {
                issue_g2(sb, 1, t, qb, 1);                    // step 9 -> parity 1
                cp_commit();
            } else if (q < P_ - 1) {
                issue_g1(sb, 0, t, qb + B_, pb, j0, 0, 0);    // step 10 -> parity 0
                cp_commit();
            }
            const uint32_t bA2 = sb + kc * STG;
#pragma unroll
            for (int s = 0; s < 8; s++) {
                const int plane = s >> 2;
                const uint32_t scol = (uint32_t)((s & 3) * 32);
                const uint32_t pB = sb + PF + (kc * 2 + plane) * 16384;
                uint32_t ah[2][4];
#pragma unroll
                for (int mt = 0; mt < 2; mt++) {
                    const int ar = 32 * wc + 16 * mt + a_row_off;
                    const uint32_t sw = (uint32_t)((ar & 7) << 4);
                    ldm_x4(ah[mt][0], ah[mt][1], ah[mt][2], ah[mt][3],
                           bA2 + plane * 32768 + ar * 128 +
                           ((scol + (uint32_t)a_col_off) ^ sw));
                }
#pragma unroll
                for (int np = 0; np < 4; np++) {
                    const int br = 64 * wj2 + np * 16 + b_row_off;
                    const uint32_t sw = (uint32_t)((br & 7) << 4);
                    uint32_t bh[4];
                    ldm_x4(bh[0], bh[1], bh[2], bh[3],
                           pB + br * 128 + ((scol + (uint32_t)b_col_off) ^ sw));
#pragma unroll
                    for (int mt = 0; mt < 2; mt++) {
                        mma16816h(acc2[mt][2 * np],     ah[mt], bh[0], bh[1]);
                        mma16816h(acc2[mt][2 * np + 1], ah[mt], bh[2], bh[3]);
                    }
                }
            }
        }
    }

    // ===================== final epilogue: pure store ========================
    {
        float* ob = out + (size_t)pb * 65536 + j0 + 64 * wj2;
#pragma unroll
        for (int mt = 0; mt < 2; mt++) {
#pragma unroll
            for (int h = 0; h < 2; h++) {
                const int c = 32 * wc + 16 * mt + 8 * h + (lane >> 2);
                float* rowp = ob + (size_t)c * 256;
#pragma unroll
                for (int nt = 0; nt < 8; nt++) {
                    float2 o;
                    o.x = acc2[mt][nt][2 * h] * invp;
                    o.y = acc2[mt][nt][2 * h + 1] * invp;
                    *(float2*)(rowp + nt * 8 + (lane & 3) * 2) = o;
                }
            }
        }
    }
}

// ---------------------------------------------------------------------------
extern "C" void kernel_launch(void* const* d_in, const int* in_sizes, int n_in,
                              void* d_out, int out_size) {
    const float* temp = (const float*)d_in[0];
    const float* We   = (const float*)d_in[1];
    const float* Wg   = (const float*)d_in[2];
    const void*  pn   = (n_in > 3) ? d_in[3] : nullptr;
    float* out = (float*)d_out;

    transpose_split<<<dim3(8, 8, 64), 256>>>(temp);
    split_We<<<64, 256>>>(We);
    zero_wtf<<<16, 1024>>>();
    wtf_part<<<dim3(64, 8), 256>>>(temp, Wg);

    cudaFuncSetAttribute(corr_mma, cudaFuncAttributeMaxDynamicSharedMemorySize, 2 * STGC);
    corr_mma<<<dim3(2, 64), 512, 2 * STGC>>>();

    cudaFuncSetAttribute(fused_mma, cudaFuncAttributeMaxDynamicSharedMemorySize, SMEM_TOTAL);
    fused_mma<<<128, NT, SMEM_TOTAL>>>(pn, out);
}